// round 4
// baseline (speedup 1.0000x reference)
#include <cuda_runtime.h>
#include <cstdint>

typedef unsigned long long u64;

#define Bb 32
#define Tt 512
#define Dd 512
#define Hh 1024
#define Gg 4096
#define Oo 512
#define NCTA 128

// ------------------------- persistent device state -------------------------
__device__ float g_XW[(size_t)Bb * Tt * Gg];      // x@Wx0+b0, row = b*Tt+t
__device__ float g_Y [(size_t)Bb * Tt * Hh];      // h1 sequence
__device__ float g_Wt0 [(size_t)Gg * Hh];         // Wh0^T  [G,K]
__device__ float g_Wt1x[(size_t)Gg * Hh];         // Wx1^T
__device__ float g_Wt1h[(size_t)Gg * Hh];         // Wh1^T
__device__ float g_h0[2][Bb * Hh];
__device__ float g_h1[2][Bb * Hh];
__device__ unsigned g_arrive[NCTA];
__device__ unsigned g_go;

// ------------------------- small helpers -----------------------------------
__device__ __forceinline__ void fma2(u64 &d, u64 a, u64 b) {
    asm volatile("fma.rn.f32x2 %0, %1, %2, %0;" : "+l"(d) : "l"(a), "l"(b));
}
__device__ __forceinline__ u64 splat2(float x) {
    u64 r; asm("mov.b64 %0, {%1, %1};" : "=l"(r) : "f"(x)); return r;
}
__device__ __forceinline__ float2 unpack2(u64 v) {
    float2 r; asm("mov.b64 {%0, %1}, %2;" : "=f"(r.x), "=f"(r.y) : "l"(v)); return r;
}
__device__ __forceinline__ void ld128_nc(ulonglong2 &r, const float* p) {
    asm("ld.global.nc.v2.u64 {%0,%1},[%2];" : "=l"(r.x), "=l"(r.y) : "l"(p));
}
__device__ __forceinline__ void ld128_cg(ulonglong2 &r, const float* p) {
    asm volatile("ld.global.cg.v2.u64 {%0,%1},[%2];" : "=l"(r.x), "=l"(r.y) : "l"(p));
}
__device__ __forceinline__ void st_rel(unsigned* p, unsigned v) {
    asm volatile("st.release.gpu.u32 [%0],%1;" :: "l"(p), "r"(v) : "memory");
}
__device__ __forceinline__ unsigned ld_acq(const unsigned* p) {
    unsigned v; asm volatile("ld.acquire.gpu.u32 %0,[%1];" : "=r"(v) : "l"(p) : "memory");
    return v;
}
__device__ __forceinline__ float sig_(float x) { return 1.f / (1.f + __expf(-x)); }
__device__ __forceinline__ float tanh_(float x) {
    float xx = fminf(fmaxf(x, -15.f), 15.f);
    float e = __expf(-2.f * xx);
    return (1.f - e) / (1.f + e);
}

// ------------------------- init ---------------------------------------------
__global__ void init_state() {
    int i = blockIdx.x * blockDim.x + threadIdx.x;
    if (i < Bb * Hh) {
        g_h0[0][i] = 0.f; g_h0[1][i] = 0.f;
        g_h1[0][i] = 0.f; g_h1[1][i] = 0.f;
    }
    if (i < NCTA) g_arrive[i] = 0;
    if (i == 0) g_go = 0;
}

// ------------------------- weight transpose [K=1024,G=4096] -> [G,K] --------
__global__ void transpose_w(const float* __restrict__ src, float* __restrict__ dst) {
    __shared__ float t[32][33];
    int bx = blockIdx.x * 32, by = blockIdx.y * 32;
    int x = threadIdx.x, y = threadIdx.y;
#pragma unroll
    for (int i = 0; i < 32; i += 8)
        t[y + i][x] = src[(size_t)(by + y + i) * Gg + bx + x];
    __syncthreads();
#pragma unroll
    for (int i = 0; i < 32; i += 8)
        dst[(size_t)(bx + y + i) * Hh + by + x] = t[x][y + i];
}

// ------------------------- GEMM: C = A[M,K]@B[K,N] + bias -------------------
// 128x64 tile, BK=16, 256 threads, 8x4 per-thread tile with f32x2.
__global__ void __launch_bounds__(256) sgemm_bias(
        const float* __restrict__ A, const float* __restrict__ Bm,
        const float* __restrict__ bias, float* __restrict__ C,
        int M, int N, int K)
{
    __shared__ float As[16][128];
    __shared__ float Bs[16][64];
    const int tid = threadIdx.x;
    const int bm = blockIdx.y * 128;
    const int bn = blockIdx.x * 64;
    const int tn = (tid & 15) * 4;
    const int tm = (tid >> 4) * 8;

    u64 acc[4][4];
#pragma unroll
    for (int i = 0; i < 4; ++i)
#pragma unroll
        for (int j = 0; j < 4; ++j) acc[i][j] = 0ULL;

    for (int k0 = 0; k0 < K; k0 += 16) {
#pragma unroll
        for (int i = 0; i < 2; ++i) {
            int fid = tid * 2 + i;
            int r = fid >> 2, kq = fid & 3;
            float4 v = *reinterpret_cast<const float4*>(A + (size_t)(bm + r) * K + k0 + kq * 4);
            As[kq * 4 + 0][r] = v.x;
            As[kq * 4 + 1][r] = v.y;
            As[kq * 4 + 2][r] = v.z;
            As[kq * 4 + 3][r] = v.w;
        }
        {
            int kr = tid >> 4, cq = (tid & 15) * 4;
            *reinterpret_cast<float4*>(&Bs[kr][cq]) =
                *reinterpret_cast<const float4*>(Bm + (size_t)(k0 + kr) * N + bn + cq);
        }
        __syncthreads();
#pragma unroll
        for (int kk = 0; kk < 16; ++kk) {
            ulonglong2 a01 = *reinterpret_cast<const ulonglong2*>(&As[kk][tm]);
            ulonglong2 a23 = *reinterpret_cast<const ulonglong2*>(&As[kk][tm + 4]);
            float4 bv = *reinterpret_cast<const float4*>(&Bs[kk][tn]);
            u64 bs0 = splat2(bv.x), bs1 = splat2(bv.y);
            u64 bs2 = splat2(bv.z), bs3 = splat2(bv.w);
            fma2(acc[0][0], a01.x, bs0); fma2(acc[0][1], a01.x, bs1);
            fma2(acc[0][2], a01.x, bs2); fma2(acc[0][3], a01.x, bs3);
            fma2(acc[1][0], a01.y, bs0); fma2(acc[1][1], a01.y, bs1);
            fma2(acc[1][2], a01.y, bs2); fma2(acc[1][3], a01.y, bs3);
            fma2(acc[2][0], a23.x, bs0); fma2(acc[2][1], a23.x, bs1);
            fma2(acc[2][2], a23.x, bs2); fma2(acc[2][3], a23.x, bs3);
            fma2(acc[3][0], a23.y, bs0); fma2(acc[3][1], a23.y, bs1);
            fma2(acc[3][2], a23.y, bs2); fma2(acc[3][3], a23.y, bs3);
        }
        __syncthreads();
    }

    float4 bb = *reinterpret_cast<const float4*>(bias + bn + tn);
#pragma unroll
    for (int mp = 0; mp < 4; ++mp) {
        float2 p0 = unpack2(acc[mp][0]);
        float2 p1 = unpack2(acc[mp][1]);
        float2 p2 = unpack2(acc[mp][2]);
        float2 p3 = unpack2(acc[mp][3]);
        int row0 = bm + tm + mp * 2;
        float4 o0 = make_float4(p0.x + bb.x, p1.x + bb.y, p2.x + bb.z, p3.x + bb.w);
        float4 o1 = make_float4(p0.y + bb.x, p1.y + bb.y, p2.y + bb.z, p3.y + bb.w);
        *reinterpret_cast<float4*>(C + (size_t)row0 * N + bn + tn) = o0;
        *reinterpret_cast<float4*>(C + (size_t)(row0 + 1) * N + bn + tn) = o1;
    }
}

// ------------------------- recurrence building blocks -----------------------
// acc[i][j]: col (c0i+i), batch (b0+j); pair dim = K. 128 k's per chunk.
__device__ __forceinline__ void mma_chunk(u64 (&acc)[4][4],
    const float* __restrict__ w0, const float* __restrict__ w1,
    const float* __restrict__ w2, const float* __restrict__ w3,
    const float* __restrict__ h0, const float* __restrict__ h1,
    const float* __restrict__ h2, const float* __restrict__ h3)
{
#pragma unroll 4
    for (int k = 0; k < 128; k += 4) {
        ulonglong2 wa, wb, wc, wd, ha, hb, hc, hd;
        ld128_nc(wa, w0 + k); ld128_nc(wb, w1 + k);
        ld128_nc(wc, w2 + k); ld128_nc(wd, w3 + k);
        ld128_cg(ha, h0 + k); ld128_cg(hb, h1 + k);
        ld128_cg(hc, h2 + k); ld128_cg(hd, h3 + k);
        fma2(acc[0][0], wa.x, ha.x); fma2(acc[0][0], wa.y, ha.y);
        fma2(acc[0][1], wa.x, hb.x); fma2(acc[0][1], wa.y, hb.y);
        fma2(acc[0][2], wa.x, hc.x); fma2(acc[0][2], wa.y, hc.y);
        fma2(acc[0][3], wa.x, hd.x); fma2(acc[0][3], wa.y, hd.y);
        fma2(acc[1][0], wb.x, ha.x); fma2(acc[1][0], wb.y, ha.y);
        fma2(acc[1][1], wb.x, hb.x); fma2(acc[1][1], wb.y, hb.y);
        fma2(acc[1][2], wb.x, hc.x); fma2(acc[1][2], wb.y, hc.y);
        fma2(acc[1][3], wb.x, hd.x); fma2(acc[1][3], wb.y, hd.y);
        fma2(acc[2][0], wc.x, ha.x); fma2(acc[2][0], wc.y, ha.y);
        fma2(acc[2][1], wc.x, hb.x); fma2(acc[2][1], wc.y, hb.y);
        fma2(acc[2][2], wc.x, hc.x); fma2(acc[2][2], wc.y, hc.y);
        fma2(acc[2][3], wc.x, hd.x); fma2(acc[2][3], wc.y, hd.y);
        fma2(acc[3][0], wd.x, ha.x); fma2(acc[3][0], wd.y, ha.y);
        fma2(acc[3][1], wd.x, hb.x); fma2(acc[3][1], wd.y, hb.y);
        fma2(acc[3][2], wd.x, hc.x); fma2(acc[3][2], wd.y, hc.y);
        fma2(acc[3][3], wd.x, hd.x); fma2(acc[3][3], wd.y, hd.y);
    }
}

__device__ __forceinline__ void store_red(float* red, u64 (&acc)[4][4],
                                          int kc, int c0i, int b0)
{
#pragma unroll
    for (int i = 0; i < 4; ++i) {
        float2 p0 = unpack2(acc[i][0]);
        float2 p1 = unpack2(acc[i][1]);
        float2 p2 = unpack2(acc[i][2]);
        float2 p3 = unpack2(acc[i][3]);
        float4 v = make_float4(p0.x + p0.y, p1.x + p1.y, p2.x + p2.y, p3.x + p3.y);
        *reinterpret_cast<float4*>(&red[kc * 1024 + (c0i + i) * 32 + b0]) = v;
    }
}

// flag-array grid barrier; target must be monotonically increasing
__device__ __forceinline__ void grid_bar(unsigned target) {
    __syncthreads();
    const unsigned tid = threadIdx.x;
    if (tid == 0) { __threadfence(); st_rel(&g_arrive[blockIdx.x], target); }
    if (blockIdx.x == 0) {
        if (tid < NCTA) { while (ld_acq(&g_arrive[tid]) < target) {} }
        __syncthreads();
        if (tid == 0) st_rel(&g_go, target);
    }
    if (tid == 0) { while (ld_acq(&g_go) < target) {} }
    __syncthreads();
}

// ------------------------- persistent 2-layer LSTM recurrence ---------------
// Interval s: layer0 step t=s (s<T) and layer1 step t=s-1 (s>0); both read
// h0(s-1). One grid sync per interval.
__global__ void __launch_bounds__(512, 1) lstm_rec(const float* __restrict__ b1)
{
    __shared__ float red[8 * 1024];   // 32 KB, red[kc][c][b]
    const int tid = threadIdx.x;
    const int kc = tid >> 6;          // 0..7, K chunk of 128
    const int ct = (tid >> 3) & 7;    // 4 cols
    const int bt = tid & 7;           // 4 batches
    const int c0i = ct * 4;
    const int b0 = bt * 4;
    const int jbase = blockIdx.x * 8;

    size_t wcol[4];
#pragma unroll
    for (int i = 0; i < 4; ++i) {
        int c = c0i + i;
        wcol[i] = (size_t)((c >> 3) * Hh + jbase + (c & 7)) * Hh + kc * 128;
    }

    const int gb = tid >> 3;  // gate thread: batch (tid < 256)
    const int gj = tid & 7;   // gate thread: local j
    float c0s = 0.f, c1s = 0.f;
    float bias1[4];
    if (tid < 256) {
#pragma unroll
        for (int g = 0; g < 4; ++g) bias1[g] = b1[g * Hh + jbase + gj];
    }

    for (int s = 0; s <= Tt; ++s) {
        const int rb = (s + 1) & 1;
        const int wb = s & 1;

        float xw[4];
        if (tid < 256 && s < Tt) {
#pragma unroll
            for (int g = 0; g < 4; ++g)
                xw[g] = __ldcg(&g_XW[((size_t)gb * Tt + s) * Gg + g * Hh + jbase + gj]);
        }

        // layer0 GEMM: h0(s-1) @ Wh0 (partials)
        if (s < Tt) {
            u64 acc[4][4];
#pragma unroll
            for (int i = 0; i < 4; ++i)
#pragma unroll
                for (int j = 0; j < 4; ++j) acc[i][j] = 0ULL;
            const float* hp = g_h0[rb];
            const int ko = kc * 128;
            mma_chunk(acc,
                g_Wt0 + wcol[0], g_Wt0 + wcol[1], g_Wt0 + wcol[2], g_Wt0 + wcol[3],
                hp + (b0 + 0) * Hh + ko, hp + (b0 + 1) * Hh + ko,
                hp + (b0 + 2) * Hh + ko, hp + (b0 + 3) * Hh + ko);
            store_red(red, acc, kc, c0i, b0);
        }
        __syncthreads();

        // gate threads pull z0 into registers (red gets reused by layer1)
        float z0[4];
        if (tid < 256 && s < Tt) {
#pragma unroll
            for (int g = 0; g < 4; ++g) {
                float t = xw[g];
#pragma unroll
                for (int kk = 0; kk < 8; ++kk)
                    t += red[kk * 1024 + (g * 8 + gj) * 32 + gb];
                z0[g] = t;
            }
        }
        __syncthreads();

        // layer1 GEMM: h0(s-1) @ Wx1 + h1(s-2) @ Wh1 (partials)
        if (s > 0) {
            u64 acc[4][4];
#pragma unroll
            for (int i = 0; i < 4; ++i)
#pragma unroll
                for (int j = 0; j < 4; ++j) acc[i][j] = 0ULL;
            const float* ha = g_h0[rb];
            const float* hc = g_h1[rb];
            const int ko = kc * 128;
            mma_chunk(acc,
                g_Wt1x + wcol[0], g_Wt1x + wcol[1], g_Wt1x + wcol[2], g_Wt1x + wcol[3],
                ha + (b0 + 0) * Hh + ko, ha + (b0 + 1) * Hh + ko,
                ha + (b0 + 2) * Hh + ko, ha + (b0 + 3) * Hh + ko);
            mma_chunk(acc,
                g_Wt1h + wcol[0], g_Wt1h + wcol[1], g_Wt1h + wcol[2], g_Wt1h + wcol[3],
                hc + (b0 + 0) * Hh + ko, hc + (b0 + 1) * Hh + ko,
                hc + (b0 + 2) * Hh + ko, hc + (b0 + 3) * Hh + ko);
            store_red(red, acc, kc, c0i, b0);
        }
        __syncthreads();

        // gates
        if (tid < 256) {
            if (s < Tt) {
                float ci = sig_(z0[0]), cf = sig_(z0[1]);
                float cg = tanh_(z0[2]), co = sig_(z0[3]);
                c0s = cf * c0s + ci * cg;
                g_h0[wb][gb * Hh + jbase + gj] = co * tanh_(c0s);
            }
            if (s > 0) {
                float z1[4];
#pragma unroll
                for (int g = 0; g < 4; ++g) {
                    float t = bias1[g];
#pragma unroll
                    for (int kk = 0; kk < 8; ++kk)
                        t += red[kk * 1024 + (g * 8 + gj) * 32 + gb];
                    z1[g] = t;
                }
                float ci = sig_(z1[0]), cf = sig_(z1[1]);
                float cg = tanh_(z1[2]), co = sig_(z1[3]);
                c1s = cf * c1s + ci * cg;
                float hn = co * tanh_(c1s);
                g_h1[wb][gb * Hh + jbase + gj] = hn;
                g_Y[((size_t)gb * Tt + (s - 1)) * Hh + jbase + gj] = hn;
            }
        }
        grid_bar((unsigned)(s + 1));
    }
}

// ------------------------- launch --------------------------------------------
extern "C" void kernel_launch(void* const* d_in, const int* in_sizes, int n_in,
                              void* d_out, int out_size)
{
    const float* x   = (const float*)d_in[0];
    const float* Wx0 = (const float*)d_in[1];
    const float* Wh0 = (const float*)d_in[2];
    // b0 folded into XW via sgemm bias: d_in[3]
    const float* b0v = (const float*)d_in[3];
    const float* Wx1 = (const float*)d_in[4];
    const float* Wh1 = (const float*)d_in[5];
    const float* b1v = (const float*)d_in[6];
    const float* Wd  = (const float*)d_in[7];
    const float* bdv = (const float*)d_in[8];
    float* out = (float*)d_out;

    float* xw;  cudaGetSymbolAddress((void**)&xw,  g_XW);
    float* yv;  cudaGetSymbolAddress((void**)&yv,  g_Y);
    float* wt0; cudaGetSymbolAddress((void**)&wt0, g_Wt0);
    float* wt1x; cudaGetSymbolAddress((void**)&wt1x, g_Wt1x);
    float* wt1h; cudaGetSymbolAddress((void**)&wt1h, g_Wt1h);

    init_state<<<64, 512>>>();
    dim3 tb(32, 8), tg(Gg / 32, Hh / 32);
    transpose_w<<<tg, tb>>>(Wh0, wt0);
    transpose_w<<<tg, tb>>>(Wx1, wt1x);
    transpose_w<<<tg, tb>>>(Wh1, wt1h);

    // XW = x @ Wx0 + b0   [16384, 4096]
    sgemm_bias<<<dim3(Gg / 64, (Bb * Tt) / 128), 256>>>(x, Wx0, b0v, xw,
                                                        Bb * Tt, Gg, Dd);
    // recurrence
    lstm_rec<<<NCTA, 512>>>(b1v);

    // out = Y @ Wd + bd   [16384, 512]
    sgemm_bias<<<dim3(Oo / 64, (Bb * Tt) / 128), 256>>>(yv, Wd, bdv, out,
                                                        Bb * Tt, Oo, Hh);
}